// round 14
// baseline (speedup 1.0000x reference)
#include <cuda_runtime.h>
#include <cstdint>
#include <cstddef>

#define T_DIM 256
#define B_DIM 2048
#define DIN   128
#define NQ    16
#define GN    64
#define M_TOT (T_DIM * B_DIM)

// ZX scratch padded by 4 timesteps so phase-2 prefetch needs no bounds check.
__device__ __align__(256) float g_zx[(size_t)(T_DIM + 4) * B_DIM * GN];

// ===========================================================================
// Phase 1 (R13, measured ~127us): mma.sync m16n8k16 fp16, 2xFP16 split
// (X = Xh + Xl, W single fp16).
// ===========================================================================
#define SROW8 20
#define WROW  12

__device__ __forceinline__ uint2 f16_split2(float x, float y) {
    uint32_t h, l;
    asm("cvt.rn.f16x2.f32 %0, %1, %2;" : "=r"(h) : "f"(y), "f"(x));
    float hx, hy;
    asm("{\n\t.reg .b16 lo, hi;\n\tmov.b32 {lo, hi}, %2;\n\t"
        "cvt.f32.f16 %0, lo;\n\tcvt.f32.f16 %1, hi;\n\t}"
        : "=f"(hx), "=f"(hy) : "r"(h));
    asm("cvt.rn.f16x2.f32 %0, %1, %2;" : "=r"(l) : "f"(y - hy), "f"(x - hx));
    return make_uint2(h, l);
}
__device__ __forceinline__ uint32_t f16x2_of(float x, float y) {
    uint32_t r;
    asm("cvt.rn.f16x2.f32 %0, %1, %2;" : "=r"(r) : "f"(y), "f"(x));
    return r;
}

#define MMA_FP16(c, a0, a1, a2, a3, b0, b1) \
    asm volatile("mma.sync.aligned.m16n8k16.row.col.f32.f16.f16.f32 " \
        "{%0,%1,%2,%3}, {%4,%5,%6,%7}, {%8,%9}, {%0,%1,%2,%3};" \
        : "+f"((c)[0]), "+f"((c)[1]), "+f"((c)[2]), "+f"((c)[3]) \
        : "r"(a0), "r"(a1), "r"(a2), "r"(a3), "r"(b0), "r"(b1))

__global__ __launch_bounds__(256, 2) void qlstm_p1(
    const float* __restrict__ X,
    const float* __restrict__ W,      // [64][144]
    const float* __restrict__ Bb,
    const float* __restrict__ Th)
{
    __shared__ float bts[64];
    __shared__ uint2 Wp[64 * WROW];
    __shared__ uint2 Xs2[256 * SROW8];

    const int tid  = threadIdx.x;
    const int lane = tid & 31, w = tid >> 5;
    const int g = lane >> 2, tig = lane & 3;
    const int rb = w * 32;
    const size_t m0 = (size_t)blockIdx.x * 256;

    if (tid < 64) bts[tid] = Bb[tid] + Th[tid];

    const int sr = tid >> 3, sq = tid & 7;
    const int kp0 = 2 * sq, kp1 = 2 * sq + 1;
    const int j0 = ((kp0 >> 3) << 2) | (kp0 & 3), h0 = (kp0 >> 2) & 1;
    const int j1 = ((kp1 >> 3) << 2) | (kp1 & 3), h1 = (kp1 >> 2) & 1;

    float C[2][8][4];
#pragma unroll
    for (int s = 0; s < 2; s++)
#pragma unroll
        for (int nt = 0; nt < 8; nt++)
#pragma unroll
            for (int q = 0; q < 4; q++) C[s][nt][q] = 0.0f;

    float4 xr[8], wr[2];
#pragma unroll
    for (int i = 0; i < 8; i++)
        xr[i] = *(const float4*)(X + (m0 + sr + 32 * i) * DIN + 4 * sq);
#pragma unroll
    for (int i = 0; i < 2; i++)
        wr[i] = *(const float4*)(W + (sr + 32 * i) * 144 + 4 * sq);

    for (int kc = 0; kc < 4; kc++) {
#pragma unroll
        for (int i = 0; i < 8; i++) {
            const uint2 u0 = f16_split2(xr[i].x, xr[i].y);
            const uint2 u1 = f16_split2(xr[i].z, xr[i].w);
            *(uint4*)&Xs2[(sr + 32 * i) * SROW8 + 2 * sq] =
                make_uint4(u0.x, u0.y, u1.x, u1.y);
        }
#pragma unroll
        for (int i = 0; i < 2; i++) {
            const int row = sr + 32 * i;
            ((uint32_t*)&Wp[row * WROW + j0])[h0] = f16x2_of(wr[i].x, wr[i].y);
            ((uint32_t*)&Wp[row * WROW + j1])[h1] = f16x2_of(wr[i].z, wr[i].w);
        }
        __syncthreads();

        if (kc < 3) {
            const int kb = (kc + 1) * 32;
#pragma unroll
            for (int i = 0; i < 8; i++)
                xr[i] = *(const float4*)(X + (m0 + sr + 32 * i) * DIN + kb + 4 * sq);
#pragma unroll
            for (int i = 0; i < 2; i++)
                wr[i] = *(const float4*)(W + (sr + 32 * i) * 144 + kb + 4 * sq);
        }

#pragma unroll
        for (int ks = 0; ks < 2; ks++) {
            const int kp = ks * 8 + tig;
            const uint2 A0 = Xs2[(rb + g) * SROW8 + kp];
            const uint2 A1 = Xs2[(rb + 8 + g) * SROW8 + kp];
            const uint2 A2 = Xs2[(rb + g) * SROW8 + kp + 4];
            const uint2 A3 = Xs2[(rb + 8 + g) * SROW8 + kp + 4];
            const uint2 D0 = Xs2[(rb + 16 + g) * SROW8 + kp];
            const uint2 D1 = Xs2[(rb + 24 + g) * SROW8 + kp];
            const uint2 D2 = Xs2[(rb + 16 + g) * SROW8 + kp + 4];
            const uint2 D3 = Xs2[(rb + 24 + g) * SROW8 + kp + 4];
            const int bslot = ks * 4 + tig;
#pragma unroll
            for (int nt = 0; nt < 8; nt++) {
                const uint2 Bp = Wp[(nt * 8 + g) * WROW + bslot];
                MMA_FP16(C[0][nt], A0.x, A1.x, A2.x, A3.x, Bp.x, Bp.y);
                MMA_FP16(C[0][nt], A0.y, A1.y, A2.y, A3.y, Bp.x, Bp.y);
                MMA_FP16(C[1][nt], D0.x, D1.x, D2.x, D3.x, Bp.x, Bp.y);
                MMA_FP16(C[1][nt], D0.y, D1.y, D2.y, D3.y, Bp.x, Bp.y);
            }
        }
        __syncthreads();
    }

    float2 bt2[8];
#pragma unroll
    for (int nt = 0; nt < 8; nt++)
        bt2[nt] = *(const float2*)&bts[nt * 8 + 2 * tig];

#pragma unroll
    for (int s = 0; s < 2; s++) {
        const size_t r0 = m0 + rb + 16 * s + g;
#pragma unroll
        for (int nt = 0; nt < 8; nt++) {
            const int col = nt * 8 + 2 * tig;
            *(float2*)&g_zx[r0 * GN + col] =
                make_float2(C[s][nt][0] + bt2[nt].x, C[s][nt][1] + bt2[nt].y);
            *(float2*)&g_zx[(r0 + 8) * GN + col] =
                make_float2(C[s][nt][2] + bt2[nt].x, C[s][nt][3] + bt2[nt].y);
        }
    }
}

// ===========================================================================
// Phase 2: 16 lanes per element, TWO elements per lane (interleaved
// independent chains for ILP). Block 64 thr = 4 groups x 2 elements = 8
// elements; grid 256. Weights shared across chains. 2-step prefetch groups.
// ===========================================================================
#define FMA_X2(d, a, b, c) \
    asm("fma.rn.f32x2 %0, %1, %2, %3;" : "=l"(d) : "l"(a), "l"(b), "l"(c))
#define PACK2(d, x, y) \
    asm("mov.b64 %0, {%1, %2};" : "=l"(d) : "f"(x), "f"(y))
#define UNPACK2(x, y, d) \
    asm("mov.b64 {%0, %1}, %2;" : "=f"(x), "=f"(y) : "l"(d))

#define SA1 0.25f
#define SA3 (-2.0833333e-2f)
#define SA5 (2.0833333e-3f)
#define SA7 (-2.1081349e-4f)
#define SA9 (2.1356922e-5f)
__device__ __forceinline__ float sig_poly(float q) {
    const float u = q * q;
    float p = fmaf(SA9, u, SA7);
    p = fmaf(p, u, SA5);
    p = fmaf(p, u, SA3);
    p = fmaf(p, u, SA1);
    return fmaf(p, q, 0.5f);
}
__device__ __forceinline__ float tanh_pade(float x) {
    const float u = x * x;
    const float n = fmaf(u + 105.0f, u, 945.0f);
    const float d = fmaf(fmaf(15.0f, u, 420.0f), u, 945.0f);
    return __fdividef(x * n, d);
}
__device__ __forceinline__ float scanp(float p, int n) {
    float v1 = __shfl_up_sync(0xffffffffu, p, 1, 16);
    float v2 = __shfl_up_sync(0xffffffffu, p, 2, 16);
    float v3 = __shfl_up_sync(0xffffffffu, p, 3, 16);
    float m = ((n >= 1) ? v1 : 1.0f) * ((n >= 2) ? v2 : 1.0f);
    p *= m * ((n >= 3) ? v3 : 1.0f);
    float w1 = __shfl_up_sync(0xffffffffu, p, 4, 16);
    float w2 = __shfl_up_sync(0xffffffffu, p, 8, 16);
    float w3 = __shfl_up_sync(0xffffffffu, p, 12, 16);
    float mm = ((n >= 4) ? w1 : 1.0f) * ((n >= 8) ? w2 : 1.0f);
    return p * (mm * ((n >= 12) ? w3 : 1.0f));
}

__global__ void qlstm_p2(
    const float* __restrict__ W, float* __restrict__ out, const int write_final)
{
    __shared__ float hs[2][2][4][16];   // [step parity][chain j][grp][n]

    const int tid = threadIdx.x;
    const int n   = tid & 15;
    const int grp = tid >> 4;            // 0..3
    const int e0  = blockIdx.x * 8 + grp;
    const int e1  = e0 + 4;

    // shared packed recurrent weights: Wab[j]=(W_f,W_i), Wcd[j]=(W_g,W_o)
    unsigned long long Wab[16], Wcd[16];
#pragma unroll
    for (int j = 0; j < 16; j++) {
        const float w0 = W[(size_t)(0 * 16 + n) * 144 + 128 + j];
        const float w1 = W[(size_t)(1 * 16 + n) * 144 + 128 + j];
        const float w2 = W[(size_t)(2 * 16 + n) * 144 + 128 + j];
        const float w3 = W[(size_t)(3 * 16 + n) * 144 + 128 + j];
        PACK2(Wab[j], w0, w1);
        PACK2(Wcd[j], w2, w3);
    }

    float c[2] = {0.0f, 0.0f}, h[2] = {0.0f, 0.0f};
    hs[0][0][grp][n] = 0.0f;
    hs[0][1][grp][n] = 0.0f;
    __syncwarp();

    const size_t SS = (size_t)B_DIM * GN;
    const float* zp0 = g_zx + (size_t)e0 * GN + n;
    const float* zp1 = g_zx + (size_t)e1 * GN + n;
    float* op0 = out + (size_t)e0 * NQ + n;
    float* op1 = out + (size_t)e1 * NQ + n;

    // 2-step prefetch groups, both chains
    float zc[2][2][4];                   // [chain][step][gate]
#pragma unroll
    for (int s = 0; s < 2; s++)
#pragma unroll
        for (int g = 0; g < 4; g++) {
            zc[0][s][g] = zp0[s * SS + g * 16];
            zc[1][s][g] = zp1[s * SS + g * 16];
        }
    zp0 += 2 * SS; zp1 += 2 * SS;

    for (int tb = 0; tb < 128; ++tb) {
        float zn[2][2][4];
#pragma unroll
        for (int s = 0; s < 2; s++)
#pragma unroll
            for (int g = 0; g < 4; g++) {
                zn[0][s][g] = zp0[s * SS + g * 16];
                zn[1][s][g] = zp1[s * SS + g * 16];
            }
        zp0 += 2 * SS; zp1 += 2 * SS;

#pragma unroll
        for (int s = 0; s < 2; s++) {
            // two independent chains; bodies interleaved by the scheduler
#pragma unroll
            for (int j = 0; j < 2; j++) {
                float hv[16];
                {
                    const float4* hp = (const float4*)hs[s][j][grp];
#pragma unroll
                    for (int q = 0; q < 4; q++) {
                        const float4 v = hp[q];
                        hv[4 * q + 0] = v.x; hv[4 * q + 1] = v.y;
                        hv[4 * q + 2] = v.z; hv[4 * q + 3] = v.w;
                    }
                }
                unsigned long long ab0, ab1, cd0, cd1;
                PACK2(ab0, zc[j][s][0], zc[j][s][1]);
                PACK2(cd0, zc[j][s][2], zc[j][s][3]);
                PACK2(ab1, 0.0f, 0.0f);
                PACK2(cd1, 0.0f, 0.0f);
#pragma unroll
                for (int k = 0; k < 8; k++) {
                    unsigned long long h20, h21;
                    PACK2(h20, hv[k], hv[k]);
                    PACK2(h21, hv[k + 8], hv[k + 8]);
                    FMA_X2(ab0, h20, Wab[k], ab0);
                    FMA_X2(cd0, h20, Wcd[k], cd0);
                    FMA_X2(ab1, h21, Wab[k + 8], ab1);
                    FMA_X2(cd1, h21, Wcd[k + 8], cd1);
                }
                float za, zb, zg, zo, t0, t1;
                UNPACK2(za, zb, ab0); UNPACK2(t0, t1, ab1);
                za += t0; zb += t1;
                UNPACK2(zg, zo, cd0); UNPACK2(t0, t1, cd1);
                zg += t0; zo += t1;

                const float q0 = scanp(__cosf(za), n);
                const float q1 = scanp(__cosf(zb), n);
                const float q2 = scanp(__cosf(zg), n);
                const float q3 = scanp(__cosf(zo), n);

                const float f  = sig_poly(q0);
                const float ii = sig_poly(q1);
                const float gg = tanh_pade(q2);
                const float oo = sig_poly(q3);
                c[j] = fmaf(f, c[j], ii * gg);
                h[j] = oo * tanh_pade(c[j]);

                hs[s ^ 1][j][grp][n] = h[j];
            }
            op0[0] = h[0];
            op1[0] = h[1];
            op0 += B_DIM * NQ;
            op1 += B_DIM * NQ;
            __syncwarp();
        }
#pragma unroll
        for (int j = 0; j < 2; j++)
#pragma unroll
            for (int s = 0; s < 2; s++)
#pragma unroll
                for (int g = 0; g < 4; g++) zc[j][s][g] = zn[j][s][g];
    }

    if (write_final) {
        float* hx = out + (size_t)T_DIM * B_DIM * NQ;
        hx[(size_t)e0 * NQ + n] = h[0];
        hx[(size_t)e1 * NQ + n] = h[1];
        hx[(size_t)B_DIM * NQ + (size_t)e0 * NQ + n] = c[0];
        hx[(size_t)B_DIM * NQ + (size_t)e1 * NQ + n] = c[1];
    }
}

// ---------------------------------------------------------------------------
extern "C" void kernel_launch(void* const* d_in, const int* in_sizes, int n_in,
                              void* d_out, int out_size) {
    const float* X  = (const float*)d_in[0];
    const float* W  = (const float*)d_in[1];
    const float* Bb = (const float*)d_in[2];
    const float* Th = (const float*)d_in[3];
    float* out = (float*)d_out;

    qlstm_p1<<<M_TOT / 256, 256>>>(X, W, Bb, Th);

    const int need = T_DIM * B_DIM * NQ + 2 * B_DIM * NQ;
    const int wf = (out_size >= need) ? 1 : 0;
    qlstm_p2<<<B_DIM / 8, 64>>>(W, out, wf);
}

// round 15
// speedup vs baseline: 1.0137x; 1.0137x over previous
#include <cuda_runtime.h>
#include <cstdint>
#include <cstddef>

#define T_DIM 256
#define B_DIM 2048
#define DIN   128
#define NQ    16
#define GN    64
#define M_TOT (T_DIM * B_DIM)

// ZX scratch padded by 4 timesteps so phase-2 prefetch needs no bounds check.
__device__ __align__(256) float g_zx[(size_t)(T_DIM + 4) * B_DIM * GN];

// ===========================================================================
// Phase 1 (R13, measured ~127us): mma.sync m16n8k16 fp16, 2xFP16 split
// (X = Xh + Xl, W single fp16).
// ===========================================================================
#define SROW8 20
#define WROW  12

__device__ __forceinline__ uint2 f16_split2(float x, float y) {
    uint32_t h, l;
    asm("cvt.rn.f16x2.f32 %0, %1, %2;" : "=r"(h) : "f"(y), "f"(x));
    float hx, hy;
    asm("{\n\t.reg .b16 lo, hi;\n\tmov.b32 {lo, hi}, %2;\n\t"
        "cvt.f32.f16 %0, lo;\n\tcvt.f32.f16 %1, hi;\n\t}"
        : "=f"(hx), "=f"(hy) : "r"(h));
    asm("cvt.rn.f16x2.f32 %0, %1, %2;" : "=r"(l) : "f"(y - hy), "f"(x - hx));
    return make_uint2(h, l);
}
__device__ __forceinline__ uint32_t f16x2_of(float x, float y) {
    uint32_t r;
    asm("cvt.rn.f16x2.f32 %0, %1, %2;" : "=r"(r) : "f"(y), "f"(x));
    return r;
}

#define MMA_FP16(c, a0, a1, a2, a3, b0, b1) \
    asm volatile("mma.sync.aligned.m16n8k16.row.col.f32.f16.f16.f32 " \
        "{%0,%1,%2,%3}, {%4,%5,%6,%7}, {%8,%9}, {%0,%1,%2,%3};" \
        : "+f"((c)[0]), "+f"((c)[1]), "+f"((c)[2]), "+f"((c)[3]) \
        : "r"(a0), "r"(a1), "r"(a2), "r"(a3), "r"(b0), "r"(b1))

__global__ __launch_bounds__(256, 2) void qlstm_p1(
    const float* __restrict__ X,
    const float* __restrict__ W,      // [64][144]
    const float* __restrict__ Bb,
    const float* __restrict__ Th)
{
    __shared__ float bts[64];
    __shared__ uint2 Wp[64 * WROW];
    __shared__ uint2 Xs2[256 * SROW8];

    const int tid  = threadIdx.x;
    const int lane = tid & 31, w = tid >> 5;
    const int g = lane >> 2, tig = lane & 3;
    const int rb = w * 32;
    const size_t m0 = (size_t)blockIdx.x * 256;

    if (tid < 64) bts[tid] = Bb[tid] + Th[tid];

    const int sr = tid >> 3, sq = tid & 7;
    const int kp0 = 2 * sq, kp1 = 2 * sq + 1;
    const int j0 = ((kp0 >> 3) << 2) | (kp0 & 3), h0 = (kp0 >> 2) & 1;
    const int j1 = ((kp1 >> 3) << 2) | (kp1 & 3), h1 = (kp1 >> 2) & 1;

    float C[2][8][4];
#pragma unroll
    for (int s = 0; s < 2; s++)
#pragma unroll
        for (int nt = 0; nt < 8; nt++)
#pragma unroll
            for (int q = 0; q < 4; q++) C[s][nt][q] = 0.0f;

    float4 xr[8], wr[2];
#pragma unroll
    for (int i = 0; i < 8; i++)
        xr[i] = *(const float4*)(X + (m0 + sr + 32 * i) * DIN + 4 * sq);
#pragma unroll
    for (int i = 0; i < 2; i++)
        wr[i] = *(const float4*)(W + (sr + 32 * i) * 144 + 4 * sq);

    for (int kc = 0; kc < 4; kc++) {
#pragma unroll
        for (int i = 0; i < 8; i++) {
            const uint2 u0 = f16_split2(xr[i].x, xr[i].y);
            const uint2 u1 = f16_split2(xr[i].z, xr[i].w);
            *(uint4*)&Xs2[(sr + 32 * i) * SROW8 + 2 * sq] =
                make_uint4(u0.x, u0.y, u1.x, u1.y);
        }
#pragma unroll
        for (int i = 0; i < 2; i++) {
            const int row = sr + 32 * i;
            ((uint32_t*)&Wp[row * WROW + j0])[h0] = f16x2_of(wr[i].x, wr[i].y);
            ((uint32_t*)&Wp[row * WROW + j1])[h1] = f16x2_of(wr[i].z, wr[i].w);
        }
        __syncthreads();

        if (kc < 3) {
            const int kb = (kc + 1) * 32;
#pragma unroll
            for (int i = 0; i < 8; i++)
                xr[i] = *(const float4*)(X + (m0 + sr + 32 * i) * DIN + kb + 4 * sq);
#pragma unroll
            for (int i = 0; i < 2; i++)
                wr[i] = *(const float4*)(W + (sr + 32 * i) * 144 + kb + 4 * sq);
        }

#pragma unroll
        for (int ks = 0; ks < 2; ks++) {
            const int kp = ks * 8 + tig;
            const uint2 A0 = Xs2[(rb + g) * SROW8 + kp];
            const uint2 A1 = Xs2[(rb + 8 + g) * SROW8 + kp];
            const uint2 A2 = Xs2[(rb + g) * SROW8 + kp + 4];
            const uint2 A3 = Xs2[(rb + 8 + g) * SROW8 + kp + 4];
            const uint2 D0 = Xs2[(rb + 16 + g) * SROW8 + kp];
            const uint2 D1 = Xs2[(rb + 24 + g) * SROW8 + kp];
            const uint2 D2 = Xs2[(rb + 16 + g) * SROW8 + kp + 4];
            const uint2 D3 = Xs2[(rb + 24 + g) * SROW8 + kp + 4];
            const int bslot = ks * 4 + tig;
#pragma unroll
            for (int nt = 0; nt < 8; nt++) {
                const uint2 Bp = Wp[(nt * 8 + g) * WROW + bslot];
                MMA_FP16(C[0][nt], A0.x, A1.x, A2.x, A3.x, Bp.x, Bp.y);
                MMA_FP16(C[0][nt], A0.y, A1.y, A2.y, A3.y, Bp.x, Bp.y);
                MMA_FP16(C[1][nt], D0.x, D1.x, D2.x, D3.x, Bp.x, Bp.y);
                MMA_FP16(C[1][nt], D0.y, D1.y, D2.y, D3.y, Bp.x, Bp.y);
            }
        }
        __syncthreads();
    }

    float2 bt2[8];
#pragma unroll
    for (int nt = 0; nt < 8; nt++)
        bt2[nt] = *(const float2*)&bts[nt * 8 + 2 * tig];

#pragma unroll
    for (int s = 0; s < 2; s++) {
        const size_t r0 = m0 + rb + 16 * s + g;
#pragma unroll
        for (int nt = 0; nt < 8; nt++) {
            const int col = nt * 8 + 2 * tig;
            *(float2*)&g_zx[r0 * GN + col] =
                make_float2(C[s][nt][0] + bt2[nt].x, C[s][nt][1] + bt2[nt].y);
            *(float2*)&g_zx[(r0 + 8) * GN + col] =
                make_float2(C[s][nt][2] + bt2[nt].x, C[s][nt][3] + bt2[nt].y);
        }
    }
}

// ===========================================================================
// Phase 2: 16 lanes per element, TWO elements per lane (interleaved
// independent chains for ILP). Block 64 thr = 4 groups x 2 elements = 8
// elements; grid 256. Weights shared across chains. 2-step prefetch groups.
// ===========================================================================
#define FMA_X2(d, a, b, c) \
    asm("fma.rn.f32x2 %0, %1, %2, %3;" : "=l"(d) : "l"(a), "l"(b), "l"(c))
#define PACK2(d, x, y) \
    asm("mov.b64 %0, {%1, %2};" : "=l"(d) : "f"(x), "f"(y))
#define UNPACK2(x, y, d) \
    asm("mov.b64 {%0, %1}, %2;" : "=f"(x), "=f"(y) : "l"(d))

#define SA1 0.25f
#define SA3 (-2.0833333e-2f)
#define SA5 (2.0833333e-3f)
#define SA7 (-2.1081349e-4f)
#define SA9 (2.1356922e-5f)
__device__ __forceinline__ float sig_poly(float q) {
    const float u = q * q;
    float p = fmaf(SA9, u, SA7);
    p = fmaf(p, u, SA5);
    p = fmaf(p, u, SA3);
    p = fmaf(p, u, SA1);
    return fmaf(p, q, 0.5f);
}
__device__ __forceinline__ float tanh_pade(float x) {
    const float u = x * x;
    const float n = fmaf(u + 105.0f, u, 945.0f);
    const float d = fmaf(fmaf(15.0f, u, 420.0f), u, 945.0f);
    return __fdividef(x * n, d);
}
__device__ __forceinline__ float scanp(float p, int n) {
    float v1 = __shfl_up_sync(0xffffffffu, p, 1, 16);
    float v2 = __shfl_up_sync(0xffffffffu, p, 2, 16);
    float v3 = __shfl_up_sync(0xffffffffu, p, 3, 16);
    float m = ((n >= 1) ? v1 : 1.0f) * ((n >= 2) ? v2 : 1.0f);
    p *= m * ((n >= 3) ? v3 : 1.0f);
    float w1 = __shfl_up_sync(0xffffffffu, p, 4, 16);
    float w2 = __shfl_up_sync(0xffffffffu, p, 8, 16);
    float w3 = __shfl_up_sync(0xffffffffu, p, 12, 16);
    float mm = ((n >= 4) ? w1 : 1.0f) * ((n >= 8) ? w2 : 1.0f);
    return p * (mm * ((n >= 12) ? w3 : 1.0f));
}

__global__ void qlstm_p2(
    const float* __restrict__ W, float* __restrict__ out, const int write_final)
{
    __shared__ float hs[2][2][4][16];   // [step parity][chain j][grp][n]

    const int tid = threadIdx.x;
    const int n   = tid & 15;
    const int grp = tid >> 4;            // 0..3
    const int e0  = blockIdx.x * 8 + grp;
    const int e1  = e0 + 4;

    // shared packed recurrent weights: Wab[j]=(W_f,W_i), Wcd[j]=(W_g,W_o)
    unsigned long long Wab[16], Wcd[16];
#pragma unroll
    for (int j = 0; j < 16; j++) {
        const float w0 = W[(size_t)(0 * 16 + n) * 144 + 128 + j];
        const float w1 = W[(size_t)(1 * 16 + n) * 144 + 128 + j];
        const float w2 = W[(size_t)(2 * 16 + n) * 144 + 128 + j];
        const float w3 = W[(size_t)(3 * 16 + n) * 144 + 128 + j];
        PACK2(Wab[j], w0, w1);
        PACK2(Wcd[j], w2, w3);
    }

    float c[2] = {0.0f, 0.0f}, h[2] = {0.0f, 0.0f};
    hs[0][0][grp][n] = 0.0f;
    hs[0][1][grp][n] = 0.0f;
    __syncwarp();

    const size_t SS = (size_t)B_DIM * GN;
    const float* zp0 = g_zx + (size_t)e0 * GN + n;
    const float* zp1 = g_zx + (size_t)e1 * GN + n;
    float* op0 = out + (size_t)e0 * NQ + n;
    float* op1 = out + (size_t)e1 * NQ + n;

    // 2-step prefetch groups, both chains
    float zc[2][2][4];                   // [chain][step][gate]
#pragma unroll
    for (int s = 0; s < 2; s++)
#pragma unroll
        for (int g = 0; g < 4; g++) {
            zc[0][s][g] = zp0[s * SS + g * 16];
            zc[1][s][g] = zp1[s * SS + g * 16];
        }
    zp0 += 2 * SS; zp1 += 2 * SS;

    for (int tb = 0; tb < 128; ++tb) {
        float zn[2][2][4];
#pragma unroll
        for (int s = 0; s < 2; s++)
#pragma unroll
            for (int g = 0; g < 4; g++) {
                zn[0][s][g] = zp0[s * SS + g * 16];
                zn[1][s][g] = zp1[s * SS + g * 16];
            }
        zp0 += 2 * SS; zp1 += 2 * SS;

#pragma unroll
        for (int s = 0; s < 2; s++) {
            // two independent chains; bodies interleaved by the scheduler
#pragma unroll
            for (int j = 0; j < 2; j++) {
                float hv[16];
                {
                    const float4* hp = (const float4*)hs[s][j][grp];
#pragma unroll
                    for (int q = 0; q < 4; q++) {
                        const float4 v = hp[q];
                        hv[4 * q + 0] = v.x; hv[4 * q + 1] = v.y;
                        hv[4 * q + 2] = v.z; hv[4 * q + 3] = v.w;
                    }
                }
                unsigned long long ab0, ab1, cd0, cd1;
                PACK2(ab0, zc[j][s][0], zc[j][s][1]);
                PACK2(cd0, zc[j][s][2], zc[j][s][3]);
                PACK2(ab1, 0.0f, 0.0f);
                PACK2(cd1, 0.0f, 0.0f);
#pragma unroll
                for (int k = 0; k < 8; k++) {
                    unsigned long long h20, h21;
                    PACK2(h20, hv[k], hv[k]);
                    PACK2(h21, hv[k + 8], hv[k + 8]);
                    FMA_X2(ab0, h20, Wab[k], ab0);
                    FMA_X2(cd0, h20, Wcd[k], cd0);
                    FMA_X2(ab1, h21, Wab[k + 8], ab1);
                    FMA_X2(cd1, h21, Wcd[k + 8], cd1);
                }
                float za, zb, zg, zo, t0, t1;
                UNPACK2(za, zb, ab0); UNPACK2(t0, t1, ab1);
                za += t0; zb += t1;
                UNPACK2(zg, zo, cd0); UNPACK2(t0, t1, cd1);
                zg += t0; zo += t1;

                const float q0 = scanp(__cosf(za), n);
                const float q1 = scanp(__cosf(zb), n);
                const float q2 = scanp(__cosf(zg), n);
                const float q3 = scanp(__cosf(zo), n);

                const float f  = sig_poly(q0);
                const float ii = sig_poly(q1);
                const float gg = tanh_pade(q2);
                const float oo = sig_poly(q3);
                c[j] = fmaf(f, c[j], ii * gg);
                h[j] = oo * tanh_pade(c[j]);

                hs[s ^ 1][j][grp][n] = h[j];
            }
            op0[0] = h[0];
            op1[0] = h[1];
            op0 += B_DIM * NQ;
            op1 += B_DIM * NQ;
            __syncwarp();
        }
#pragma unroll
        for (int j = 0; j < 2; j++)
#pragma unroll
            for (int s = 0; s < 2; s++)
#pragma unroll
                for (int g = 0; g < 4; g++) zc[j][s][g] = zn[j][s][g];
    }

    if (write_final) {
        float* hx = out + (size_t)T_DIM * B_DIM * NQ;
        hx[(size_t)e0 * NQ + n] = h[0];
        hx[(size_t)e1 * NQ + n] = h[1];
        hx[(size_t)B_DIM * NQ + (size_t)e0 * NQ + n] = c[0];
        hx[(size_t)B_DIM * NQ + (size_t)e1 * NQ + n] = c[1];
    }
}

// ---------------------------------------------------------------------------
extern "C" void kernel_launch(void* const* d_in, const int* in_sizes, int n_in,
                              void* d_out, int out_size) {
    const float* X  = (const float*)d_in[0];
    const float* W  = (const float*)d_in[1];
    const float* Bb = (const float*)d_in[2];
    const float* Th = (const float*)d_in[3];
    float* out = (float*)d_out;

    qlstm_p1<<<M_TOT / 256, 256>>>(X, W, Bb, Th);

    const int need = T_DIM * B_DIM * NQ + 2 * B_DIM * NQ;
    const int wf = (out_size >= need) ? 1 : 0;
    qlstm_p2<<<B_DIM / 8, 64>>>(W, out, wf);
}